// round 5
// baseline (speedup 1.0000x reference)
#include <cuda_runtime.h>
#include <cstdint>

#define S_   4
#define B_   256
#define Q_   1024
#define P_   32768
#define D_   256
#define NB   11
#define KOUT 10
#define NEG_INF (-1e30f)

#define PT    256           // p per score tile
#define NPT   128           // P_/PT
#define QT    128           // q per score tile
#define NQT   8             // Q_/QT
#define TOPT  8             // candidates kept per (q, ptile)
#define MSEL  32            // candidates rescored per (s',q)

#define ESCALE 24.0f
#define QSCALE 16.0f

// ---------------- static device scratch ----------------
__device__ float   g_qvec [Q_ * D_];
__device__ int8_t  g_qvecs8[Q_ * D_];
__device__ int8_t  g_ents8 [(size_t)S_ * P_ * D_];               // 32MB
__device__ float   g_cand_sc[(size_t)S_ * Q_ * NPT * TOPT];      // 16MB
__device__ int     g_cand_ix[(size_t)S_ * Q_ * NPT * TOPT];      // 16MB
__device__ float   g_best_sc[S_ * Q_ * NB];
__device__ int     g_best_ix[S_ * Q_ * NB];

__device__ __forceinline__ uint32_t smem_to_u32(const void* p) {
    uint32_t a;
    asm("{ .reg .u64 t; cvta.to.shared.u64 t, %1; cvt.u32.u64 %0, t; }" : "=r"(a) : "l"(p));
    return a;
}
// 16B-chunk XOR swizzle for 256B rows (16 chunks): conflict-free ldmatrix
__device__ __forceinline__ uint32_t swz256(int row, int chunk) {
    int c = (chunk & 8) | ((chunk ^ row) & 7);
    return (uint32_t)(row * 256 + c * 16);
}
__device__ __forceinline__ void cp_async16(uint32_t smem, const void* gmem) {
    asm volatile("cp.async.cg.shared.global [%0], [%1], 16;" :: "r"(smem), "l"(gmem));
}
__device__ __forceinline__ void cp_commit_wait() {
    asm volatile("cp.async.commit_group;");
    asm volatile("cp.async.wait_group 0;");
}
__device__ __forceinline__ void ldsm_x4(uint32_t* r, uint32_t addr) {
    asm volatile("ldmatrix.sync.aligned.m8n8.x4.shared.b16 {%0,%1,%2,%3}, [%4];"
                 : "=r"(r[0]), "=r"(r[1]), "=r"(r[2]), "=r"(r[3]) : "r"(addr));
}
__device__ __forceinline__ void ldsm_x2(uint32_t* r, uint32_t addr) {
    asm volatile("ldmatrix.sync.aligned.m8n8.x2.shared.b16 {%0,%1}, [%2];"
                 : "=r"(r[0]), "=r"(r[1]) : "r"(addr));
}
// s8 x s8 -> s32, m16n8k32
__device__ __forceinline__ void mma16832_s8(int* d, const uint32_t* a, const uint32_t* b) {
    asm volatile(
        "mma.sync.aligned.m16n8k32.row.col.s32.s8.s8.s32 "
        "{%0,%1,%2,%3}, {%4,%5,%6,%7}, {%8,%9}, {%0,%1,%2,%3};"
        : "+r"(d[0]), "+r"(d[1]), "+r"(d[2]), "+r"(d[3])
        : "r"(a[0]), "r"(a[1]), "r"(a[2]), "r"(a[3]), "r"(b[0]), "r"(b[1]));
}
__device__ __forceinline__ int8_t q8(float x, float s) {
    int v = __float2int_rn(x * s);
    v = max(-127, min(127, v));
    return (int8_t)v;
}

// ============================================================
// Kernel 0a: ent f32 -> s8 (scale 24)
// ============================================================
__global__ void conv_kernel(const float* __restrict__ ent) {
    size_t i = ((size_t)blockIdx.x * blockDim.x + threadIdx.x) * 4;
    float4 v = *(const float4*)(ent + i);
    uchar4 o;
    o.x = (uint8_t)q8(v.x, ESCALE); o.y = (uint8_t)q8(v.y, ESCALE);
    o.z = (uint8_t)q8(v.z, ESCALE); o.w = (uint8_t)q8(v.w, ESCALE);
    *(uchar4*)(g_ents8 + i) = o;
}

// ============================================================
// Kernel 0b: qvec f32 + s8 (scale 16)
// ============================================================
__global__ void qvec_kernel(const int* __restrict__ relation,
                            const int* __restrict__ head,
                            const float* __restrict__ ent,
                            const float* __restrict__ rel) {
    int q = blockIdx.x, d = threadIdx.x;
    int s = q >> 8;
    int hd = head[q], rr = relation[q];
    float v = ent[((size_t)s * P_ + hd) * D_ + d] * rel[(size_t)rr * D_ + d];
    g_qvec[q * D_ + d]   = v;
    g_qvecs8[q * D_ + d] = q8(v, QSCALE);
}

// ============================================================
// Kernel 1: IMMA s8 score + per-(q,ptile) top-8
// grid (8, 128, 4), block 512 (16 warps; warp tile 64q x 32p)
// smem: A s8 [128][256] @0 (32KB), B s8 [256][256] @32768 (64KB)
// epilogue overlay: sSc f32 [128][65] @0, sIx int [128][65] @36864
// ============================================================
#define SM_B_OFF  32768
#define SM_IX_OFF 36864
#define SM_TOTAL  98304

__global__ __launch_bounds__(512) void score_kernel() {
    extern __shared__ char sm[];
    const uint32_t sbase = smem_to_u32(sm);
    const int tid = threadIdx.x;
    const int wid = tid >> 5, lane = tid & 31;
    const int qtile = blockIdx.x, ptile = blockIdx.y, sp = blockIdx.z;

    // ---- stage A: 128 rows x 256 s8 ----
    {
        const int8_t* src = g_qvecs8 + (size_t)qtile * QT * D_;
        #pragma unroll
        for (int it = 0; it < 4; it++) {
            int i = tid + it * 512;               // 2048 chunks
            int row = i >> 4, ch = i & 15;
            cp_async16(sbase + swz256(row, ch), src + (size_t)row * D_ + ch * 16);
        }
    }
    // ---- stage B: 256 rows x 256 s8 ----
    {
        const int8_t* src = g_ents8 + ((size_t)sp * P_ + (size_t)ptile * PT) * D_;
        #pragma unroll
        for (int it = 0; it < 8; it++) {
            int i = tid + it * 512;               // 4096 chunks
            int row = i >> 4, ch = i & 15;
            cp_async16(sbase + SM_B_OFF + swz256(row, ch), src + (size_t)row * D_ + ch * 16);
        }
    }
    cp_commit_wait();
    __syncthreads();

    // ---- IMMA main loop ----
    const int wq = wid >> 3;           // 0..1
    const int wp = wid & 7;            // 0..7
    const int q0 = wq * 64, p0 = wp * 32;

    int acc[4][4][4];
    #pragma unroll
    for (int mi = 0; mi < 4; mi++)
        #pragma unroll
        for (int ni = 0; ni < 4; ni++)
            #pragma unroll
            for (int f = 0; f < 4; f++) acc[mi][ni][f] = 0;

    const int arow = (lane & 15);
    const int asel = (lane >> 4);
    const int brow = (lane & 7);
    const int bsel = ((lane >> 3) & 1);

    #pragma unroll
    for (int ks = 0; ks < 8; ks++) {   // K = 256 bytes = 8 x k32
        const int ch0 = ks * 2;
        uint32_t a[4][4], b[4][2];
        #pragma unroll
        for (int mi = 0; mi < 4; mi++)
            ldsm_x4(a[mi], sbase + swz256(q0 + mi * 16 + arow, ch0 + asel));
        #pragma unroll
        for (int ni = 0; ni < 4; ni++)
            ldsm_x2(b[ni], sbase + SM_B_OFF + swz256(p0 + ni * 8 + brow, ch0 + bsel));
        #pragma unroll
        for (int mi = 0; mi < 4; mi++)
            #pragma unroll
            for (int ni = 0; ni < 4; ni++)
                mma16832_s8(acc[mi][ni], a[mi], b[ni]);
    }
    __syncthreads();   // staged tiles no longer needed; scratch overlays them

    // ---- per-row top-8 within warp (row's 32 p live in a 4-lane group) ----
    float* sSc = (float*)sm;                 // [128][65] padded
    int*   sIx = (int*)(sm + SM_IX_OFF);     // [128][65] padded
    const int rg = lane >> 2, cg = lane & 3;

    #pragma unroll
    for (int mi = 0; mi < 4; mi++) {
        #pragma unroll
        for (int h = 0; h < 2; h++) {
            int r = q0 + mi * 16 + h * 8 + rg;       // local q row 0..127
            float v[8];
            #pragma unroll
            for (int j = 0; j < 8; j++)
                v[j] = __int2float_rn(acc[mi][j >> 1][h * 2 + (j & 1)]);
            #pragma unroll
            for (int round = 0; round < 8; round++) {
                float bv = v[0]; int bj = 0;
                #pragma unroll
                for (int j = 1; j < 8; j++) if (v[j] > bv) { bv = v[j]; bj = j; }
                int bp = p0 + (bj >> 1) * 8 + 2 * cg + (bj & 1);
                float myv = bv; int myp = bp;
                #pragma unroll
                for (int off = 1; off <= 2; off <<= 1) {
                    float ov = __shfl_xor_sync(0xffffffffu, bv, off);
                    int   op = __shfl_xor_sync(0xffffffffu, bp, off);
                    if (ov > bv || (ov == bv && op < bp)) { bv = ov; bp = op; }
                }
                if (myp == bp) {
                    v[bj] = NEG_INF;                       // remove from my set
                    sSc[r * 65 + wp * 8 + round] = myv;
                    sIx[r * 65 + wp * 8 + round] = ptile * PT + myp;
                }
            }
        }
    }
    __syncthreads();

    // ---- per-q merge of 8 sorted lists -> sorted top-8, write gmem ----
    if (tid < 128) {
        int q = qtile * QT + tid;
        size_t ob = (((size_t)sp * Q_ + q) * NPT + ptile) * TOPT;
        int hh[8]; float hv[8];
        #pragma unroll
        for (int j = 0; j < 8; j++) { hh[j] = 0; hv[j] = sSc[tid * 65 + j * 8]; }
        #pragma unroll
        for (int r = 0; r < TOPT; r++) {
            float best = hv[0]; int bj = 0;
            #pragma unroll
            for (int j = 1; j < 8; j++) if (hv[j] > best) { best = hv[j]; bj = j; }
            g_cand_sc[ob + r] = best;
            g_cand_ix[ob + r] = sIx[tid * 65 + bj * 8 + hh[bj]];
            hh[bj]++;
            hv[bj] = (hh[bj] < 8) ? sSc[tid * 65 + bj * 8 + hh[bj]] : NEG_INF;
        }
    }
}

// ============================================================
// Kernel 2: per (s',q): tournament over 128 sorted top-8 lists
// -> approx top-32, exact f32 rescore, exact top-11.
// grid 4096, block 256
// ============================================================
__global__ __launch_bounds__(256) void select_kernel(const float* __restrict__ ent) {
    __shared__ float cs_t[TOPT][NPT];      // [rank][list]
    __shared__ int   ci_t[TOPT][NPT];
    __shared__ int   sel_ix[MSEL];
    __shared__ float partial[MSEL][8];
    __shared__ float fsc[MSEL];

    const int tid = threadIdx.x;
    const int pair = blockIdx.x;
    const int sp = pair >> 10, q = pair & 1023;
    size_t base = ((size_t)sp * Q_ + q) * (size_t)(NPT * TOPT);

    for (int e = tid; e < NPT * TOPT; e += 256) {
        cs_t[e & 7][e >> 3] = g_cand_sc[base + e];
        ci_t[e & 7][e >> 3] = g_cand_ix[base + e];
    }
    __syncthreads();

    // warp 0: tournament; lane owns 4 lists with register heads
    if (tid < 32) {
        int   h[4];
        float hv[4];
        #pragma unroll
        for (int j = 0; j < 4; j++) { h[j] = 0; hv[j] = cs_t[0][tid * 4 + j]; }
        for (int r = 0; r < MSEL; r++) {
            float best = hv[0]; int bj = 0;
            #pragma unroll
            for (int j = 1; j < 4; j++) if (hv[j] > best) { best = hv[j]; bj = j; }
            float bv = best; int bl = tid;
            #pragma unroll
            for (int off = 16; off > 0; off >>= 1) {
                float ov = __shfl_down_sync(0xffffffffu, bv, off);
                int   ol = __shfl_down_sync(0xffffffffu, bl, off);
                if (ov > bv) { bv = ov; bl = ol; }
            }
            bl = __shfl_sync(0xffffffffu, bl, 0);
            if (tid == bl) {
                int list = tid * 4 + bj;
                sel_ix[r] = ci_t[h[bj]][list];
                h[bj]++;
                hv[bj] = (h[bj] < TOPT) ? cs_t[h[bj]][list] : NEG_INF;
            }
            __syncwarp();
        }
    }
    __syncthreads();

    // exact f32 rescore: 8 threads per candidate, 32 candidates
    {
        int c = tid >> 3, part = tid & 7;
        int p = sel_ix[c];
        const float4* qv = (const float4*)(g_qvec + (size_t)q * D_ + part * 32);
        const float4* ev = (const float4*)(ent + ((size_t)sp * P_ + p) * D_ + part * 32);
        float accv = 0.f;
        #pragma unroll
        for (int i = 0; i < 8; i++) {
            float4 a = qv[i], e = ev[i];
            accv = fmaf(a.x, e.x, fmaf(a.y, e.y, fmaf(a.z, e.z, fmaf(a.w, e.w, accv))));
        }
        partial[c][part] = accv;
    }
    __syncthreads();
    if (tid < MSEL) {
        float s = 0.f;
        #pragma unroll
        for (int j = 0; j < 8; j++) s += partial[tid][j];
        fsc[tid] = s;
    }
    __syncthreads();

    // warp 0: exact top-11 of 32
    if (tid < 32) {
        float v = fsc[tid];
        int ix = sel_ix[tid];
        size_t ob = ((size_t)sp * Q_ + q) * NB;
        for (int r = 0; r < NB; r++) {
            float bv = v; int bl = tid;
            #pragma unroll
            for (int off = 16; off > 0; off >>= 1) {
                float ov = __shfl_down_sync(0xffffffffu, bv, off);
                int   ol = __shfl_down_sync(0xffffffffu, bl, off);
                if (ov > bv) { bv = ov; bl = ol; }
            }
            bl = __shfl_sync(0xffffffffu, bl, 0);
            float wv = __shfl_sync(0xffffffffu, v, bl);
            int   wi = __shfl_sync(0xffffffffu, ix, bl);
            if (tid == 0) { g_best_sc[ob + r] = wv; g_best_ix[ob + r] = wi; }
            if (tid == bl) v = NEG_INF;
            __syncwarp();
        }
    }
}

// ============================================================
// Kernel 3: per (s,b) merge 4 x 11 -> top-10; write output
// ============================================================
__global__ void final_kernel(float* __restrict__ out) {
    int q = blockIdx.x * blockDim.x + threadIdx.x;
    if (q >= Q_) return;
    float bs[KOUT]; int bg[KOUT];
    #pragma unroll
    for (int r = 0; r < KOUT; r++) { bs[r] = NEG_INF; bg[r] = -1; }
    for (int sp = 0; sp < S_; sp++) {
        size_t base = ((size_t)sp * Q_ + q) * NB;
        for (int r = 0; r < NB; r++) {
            float v = g_best_sc[base + r];
            if (v > bs[KOUT - 1]) {
                int gid = g_best_ix[base + r] * S_ + sp;
                float cv = v; int ci = gid;
                #pragma unroll
                for (int k = 0; k < KOUT; k++) {
                    if (cv > bs[k]) {
                        float t0 = bs[k]; int t1 = bg[k];
                        bs[k] = cv; bg[k] = ci; cv = t0; ci = t1;
                    }
                }
            }
        }
    }
    #pragma unroll
    for (int k = 0; k < KOUT; k++) {
        out[q * KOUT + k]             = (float)bg[k];
        out[Q_ * KOUT + q * KOUT + k] = bs[k];
    }
}

// ============================================================
extern "C" void kernel_launch(void* const* d_in, const int* in_sizes, int n_in,
                              void* d_out, int out_size) {
    const int*   relation = (const int*)d_in[0];
    const int*   head     = (const int*)d_in[1];
    const float* ent      = (const float*)d_in[2];
    const float* rel      = (const float*)d_in[3];
    float* out = (float*)d_out;

    cudaFuncSetAttribute(score_kernel, cudaFuncAttributeMaxDynamicSharedMemorySize, SM_TOTAL);

    conv_kernel<<<(int)(((size_t)S_ * P_ * D_ / 4) / 256), 256>>>(ent);
    qvec_kernel<<<Q_, D_>>>(relation, head, ent, rel);
    dim3 g1(NQT, NPT, S_);
    score_kernel<<<g1, 512, SM_TOTAL>>>();
    select_kernel<<<S_ * Q_, 256>>>(ent);
    final_kernel<<<4, 256>>>(out);
}

// round 6
// speedup vs baseline: 1.0611x; 1.0611x over previous
#include <cuda_runtime.h>
#include <cstdint>

#define S_   4
#define B_   256
#define Q_   1024
#define P_   32768
#define D_   256
#define NB   11
#define KOUT 10
#define NEG_INF (-1e30f)
#define NEG_I   (-2147483647)

#define PT    256           // p per score tile
#define NPT   128           // P_/PT
#define QT    128           // q per score tile
#define NQT   8             // Q_/QT
#define TOPT  8             // candidates kept per (q, ptile)
#define MSEL  32            // candidates rescored per (s',q)

#define ESCALE 24.0f
#define QSCALE 16.0f

// ---------------- static device scratch ----------------
__device__ float   g_qvec  [Q_ * D_];
__device__ int8_t  g_qvecs8[Q_ * D_];
__device__ int8_t  g_ents8 [(size_t)S_ * P_ * D_];               // 32MB
__device__ float   g_cand_sc[(size_t)S_ * Q_ * NPT * TOPT];      // 16MB
__device__ int     g_cand_ix[(size_t)S_ * Q_ * NPT * TOPT];      // 16MB
__device__ float   g_best_sc[S_ * Q_ * NB];
__device__ int     g_best_ix[S_ * Q_ * NB];

__device__ __forceinline__ uint32_t smem_to_u32(const void* p) {
    uint32_t a;
    asm("{ .reg .u64 t; cvta.to.shared.u64 t, %1; cvt.u32.u64 %0, t; }" : "=r"(a) : "l"(p));
    return a;
}
// 16B-chunk XOR swizzle for 256B rows (16 chunks): conflict-free ldmatrix
__device__ __forceinline__ uint32_t swz256(int row, int chunk) {
    int c = (chunk & 8) | ((chunk ^ row) & 7);
    return (uint32_t)(row * 256 + c * 16);
}
__device__ __forceinline__ void cp_async16(uint32_t smem, const void* gmem) {
    asm volatile("cp.async.cg.shared.global [%0], [%1], 16;" :: "r"(smem), "l"(gmem));
}
__device__ __forceinline__ void cp_commit_wait() {
    asm volatile("cp.async.commit_group;");
    asm volatile("cp.async.wait_group 0;");
}
__device__ __forceinline__ void ldsm_x4(uint32_t* r, uint32_t addr) {
    asm volatile("ldmatrix.sync.aligned.m8n8.x4.shared.b16 {%0,%1,%2,%3}, [%4];"
                 : "=r"(r[0]), "=r"(r[1]), "=r"(r[2]), "=r"(r[3]) : "r"(addr));
}
__device__ __forceinline__ void ldsm_x2(uint32_t* r, uint32_t addr) {
    asm volatile("ldmatrix.sync.aligned.m8n8.x2.shared.b16 {%0,%1}, [%2];"
                 : "=r"(r[0]), "=r"(r[1]) : "r"(addr));
}
// s8 x s8 -> s32, m16n8k32
__device__ __forceinline__ void mma16832_s8(int* d, const uint32_t* a, const uint32_t* b) {
    asm volatile(
        "mma.sync.aligned.m16n8k32.row.col.s32.s8.s8.s32 "
        "{%0,%1,%2,%3}, {%4,%5,%6,%7}, {%8,%9}, {%0,%1,%2,%3};"
        : "+r"(d[0]), "+r"(d[1]), "+r"(d[2]), "+r"(d[3])
        : "r"(a[0]), "r"(a[1]), "r"(a[2]), "r"(a[3]), "r"(b[0]), "r"(b[1]));
}
__device__ __forceinline__ int8_t q8(float x, float s) {
    int v = __float2int_rn(x * s);
    v = max(-127, min(127, v));
    return (int8_t)v;
}

// ============================================================
// Kernel 0a: ent f32 -> s8 (scale 24)
// ============================================================
__global__ void conv_kernel(const float* __restrict__ ent) {
    size_t i = ((size_t)blockIdx.x * blockDim.x + threadIdx.x) * 4;
    float4 v = *(const float4*)(ent + i);
    uchar4 o;
    o.x = (uint8_t)q8(v.x, ESCALE); o.y = (uint8_t)q8(v.y, ESCALE);
    o.z = (uint8_t)q8(v.z, ESCALE); o.w = (uint8_t)q8(v.w, ESCALE);
    *(uchar4*)(g_ents8 + i) = o;
}

// ============================================================
// Kernel 0b: qvec f32 + s8 (scale 16)
// ============================================================
__global__ void qvec_kernel(const int* __restrict__ relation,
                            const int* __restrict__ head,
                            const float* __restrict__ ent,
                            const float* __restrict__ rel) {
    int q = blockIdx.x, d = threadIdx.x;
    int s = q >> 8;
    int hd = head[q], rr = relation[q];
    float v = ent[((size_t)s * P_ + hd) * D_ + d] * rel[(size_t)rr * D_ + d];
    g_qvec[q * D_ + d]   = v;
    g_qvecs8[q * D_ + d] = q8(v, QSCALE);
}

// ============================================================
// Kernel 1: IMMA s8 score + per-(q,ptile) top-8 (int scan)
// grid (8, 128, 4), block 512 (16 warps; warp tile 64q x 32p)
// smem: A s8 [128][256] @0 (32KB), B s8 [256][256] @32768 (64KB)
// epilogue overlay: sS int [128][260] @0 (133120B),
//   scr_sc int @133120 (16KB), scr_ix @149504 (16KB)
// ============================================================
#define SM_B_OFF   32768
#define SM_SS_STR  260
#define SM_SCR_SC  133120
#define SM_SCR_IX  149504
#define SM_TOTAL   165888

__global__ __launch_bounds__(512) void score_kernel() {
    extern __shared__ char sm[];
    const uint32_t sbase = smem_to_u32(sm);
    const int tid = threadIdx.x;
    const int wid = tid >> 5, lane = tid & 31;
    const int qtile = blockIdx.x, ptile = blockIdx.y, sp = blockIdx.z;

    // ---- stage A: 128 rows x 256 s8 ----
    {
        const int8_t* src = g_qvecs8 + (size_t)qtile * QT * D_;
        #pragma unroll
        for (int it = 0; it < 4; it++) {
            int i = tid + it * 512;               // 2048 chunks
            int row = i >> 4, ch = i & 15;
            cp_async16(sbase + swz256(row, ch), src + (size_t)row * D_ + ch * 16);
        }
    }
    // ---- stage B: 256 rows x 256 s8 ----
    {
        const int8_t* src = g_ents8 + ((size_t)sp * P_ + (size_t)ptile * PT) * D_;
        #pragma unroll
        for (int it = 0; it < 8; it++) {
            int i = tid + it * 512;               // 4096 chunks
            int row = i >> 4, ch = i & 15;
            cp_async16(sbase + SM_B_OFF + swz256(row, ch), src + (size_t)row * D_ + ch * 16);
        }
    }
    cp_commit_wait();
    __syncthreads();

    // ---- IMMA main loop ----
    const int wq = wid >> 3;           // 0..1
    const int wp = wid & 7;            // 0..7
    const int q0 = wq * 64, p0 = wp * 32;

    int acc[4][4][4];
    #pragma unroll
    for (int mi = 0; mi < 4; mi++)
        #pragma unroll
        for (int ni = 0; ni < 4; ni++)
            #pragma unroll
            for (int f = 0; f < 4; f++) acc[mi][ni][f] = 0;

    const int arow = (lane & 15);
    const int asel = (lane >> 4);
    const int brow = (lane & 7);
    const int bsel = ((lane >> 3) & 1);

    #pragma unroll
    for (int ks = 0; ks < 8; ks++) {   // K = 256 bytes = 8 x k32
        const int ch0 = ks * 2;
        uint32_t a[4][4], b[4][2];
        #pragma unroll
        for (int mi = 0; mi < 4; mi++)
            ldsm_x4(a[mi], sbase + swz256(q0 + mi * 16 + arow, ch0 + asel));
        #pragma unroll
        for (int ni = 0; ni < 4; ni++)
            ldsm_x2(b[ni], sbase + SM_B_OFF + swz256(p0 + ni * 8 + brow, ch0 + bsel));
        #pragma unroll
        for (int mi = 0; mi < 4; mi++)
            #pragma unroll
            for (int ni = 0; ni < 4; ni++)
                mma16832_s8(acc[mi][ni], a[mi], b[ni]);
    }
    __syncthreads();   // staged tiles no longer needed; scratch overlays them

    // ---- dump int scores -> smem [128][260] ----
    int* sS = (int*)sm;
    {
        int rr = lane >> 2, cc = 2 * (lane & 3);
        #pragma unroll
        for (int mi = 0; mi < 4; mi++)
            #pragma unroll
            for (int ni = 0; ni < 4; ni++) {
                int r = q0 + mi * 16 + rr;
                int c = p0 + ni * 8 + cc;
                sS[r * SM_SS_STR + c]           = acc[mi][ni][0];
                sS[r * SM_SS_STR + c + 1]       = acc[mi][ni][1];
                sS[(r + 8) * SM_SS_STR + c]     = acc[mi][ni][2];
                sS[(r + 8) * SM_SS_STR + c + 1] = acc[mi][ni][3];
            }
    }
    __syncthreads();

    // ---- per-thread int top-8 over 64 interleaved p's ----
    int* scr_sc = (int*)(sm + SM_SCR_SC);
    int* scr_ix = (int*)(sm + SM_SCR_IX);
    const int tq = tid >> 2, tsg = tid & 3;
    const int pg0 = ptile * PT;
    {
        int bs[TOPT]; int bi[TOPT];
        #pragma unroll
        for (int r = 0; r < TOPT; r++) { bs[r] = NEG_I; bi[r] = 0; }
        for (int i = 0; i < 64; i++) {
            int p = tsg + (i << 2);
            int v = sS[tq * SM_SS_STR + p];
            if (v > bs[TOPT - 1]) {
                int cv = v; int ci = pg0 + p;
                #pragma unroll
                for (int r = 0; r < TOPT; r++) {
                    if (cv > bs[r]) {
                        int t0 = bs[r]; int t1 = bi[r];
                        bs[r] = cv; bi[r] = ci; cv = t0; ci = t1;
                    }
                }
            }
        }
        #pragma unroll
        for (int r = 0; r < TOPT; r++) {
            scr_sc[(tq * 4 + tsg) * TOPT + r] = bs[r];
            scr_ix[(tq * 4 + tsg) * TOPT + r] = bi[r];
        }
    }
    __syncthreads();

    // ---- leader: merge 4 sorted top-8 lists -> sorted top-8, write ----
    if (tsg == 0) {
        int q = qtile * QT + tq;
        size_t ob = (((size_t)sp * Q_ + q) * NPT + ptile) * TOPT;
        int h0 = 0, h1 = 0, h2 = 0, h3 = 0;
        const int* L = scr_sc + (size_t)tq * 4 * TOPT;
        const int* X = scr_ix + (size_t)tq * 4 * TOPT;
        #pragma unroll
        for (int r = 0; r < TOPT; r++) {
            int best = NEG_I; int bj = 0, bh = 0;
            #define TRYM(j, h) { int v = ((h) < TOPT) ? L[(j) * TOPT + (h)] : NEG_I; \
                                 if (v > best) { best = v; bj = (j); bh = (h); } }
            TRYM(0, h0) TRYM(1, h1) TRYM(2, h2) TRYM(3, h3)
            #undef TRYM
            g_cand_sc[ob + r] = (float)best;       // exact: |best| < 2^22
            g_cand_ix[ob + r] = X[bj * TOPT + bh];
            if      (bj == 0) h0++;
            else if (bj == 1) h1++;
            else if (bj == 2) h2++;
            else              h3++;
        }
    }
}

// ============================================================
// Kernel 2: per (s',q): tournament over 128 sorted top-8 lists
// -> approx top-32, exact f32 rescore, exact top-11.
// grid 4096, block 256
// ============================================================
__global__ __launch_bounds__(256) void select_kernel(const float* __restrict__ ent) {
    __shared__ float cs_t[TOPT][NPT];      // [rank][list]
    __shared__ int   ci_t[TOPT][NPT];
    __shared__ int   sel_ix[MSEL];
    __shared__ float partial[MSEL][8];
    __shared__ float fsc[MSEL];

    const int tid = threadIdx.x;
    const int pair = blockIdx.x;
    const int sp = pair >> 10, q = pair & 1023;
    size_t base = ((size_t)sp * Q_ + q) * (size_t)(NPT * TOPT);

    for (int e = tid; e < NPT * TOPT; e += 256) {
        cs_t[e & 7][e >> 3] = g_cand_sc[base + e];
        ci_t[e & 7][e >> 3] = g_cand_ix[base + e];
    }
    __syncthreads();

    // warp 0: tournament; lane owns 4 lists with register heads
    if (tid < 32) {
        int   h[4];
        float hv[4];
        #pragma unroll
        for (int j = 0; j < 4; j++) { h[j] = 0; hv[j] = cs_t[0][tid * 4 + j]; }
        for (int r = 0; r < MSEL; r++) {
            float best = hv[0]; int bj = 0;
            #pragma unroll
            for (int j = 1; j < 4; j++) if (hv[j] > best) { best = hv[j]; bj = j; }
            float bv = best; int bl = tid;
            #pragma unroll
            for (int off = 16; off > 0; off >>= 1) {
                float ov = __shfl_down_sync(0xffffffffu, bv, off);
                int   ol = __shfl_down_sync(0xffffffffu, bl, off);
                if (ov > bv) { bv = ov; bl = ol; }
            }
            bl = __shfl_sync(0xffffffffu, bl, 0);
            if (tid == bl) {
                int list = tid * 4 + bj;
                sel_ix[r] = ci_t[h[bj]][list];
                h[bj]++;
                hv[bj] = (h[bj] < TOPT) ? cs_t[h[bj]][list] : NEG_INF;
            }
            __syncwarp();
        }
    }
    __syncthreads();

    // exact f32 rescore: 8 threads per candidate, 32 candidates
    {
        int c = tid >> 3, part = tid & 7;
        int p = sel_ix[c];
        const float4* qv = (const float4*)(g_qvec + (size_t)q * D_ + part * 32);
        const float4* ev = (const float4*)(ent + ((size_t)sp * P_ + p) * D_ + part * 32);
        float accv = 0.f;
        #pragma unroll
        for (int i = 0; i < 8; i++) {
            float4 a = qv[i], e = ev[i];
            accv = fmaf(a.x, e.x, fmaf(a.y, e.y, fmaf(a.z, e.z, fmaf(a.w, e.w, accv))));
        }
        partial[c][part] = accv;
    }
    __syncthreads();
    if (tid < MSEL) {
        float s = 0.f;
        #pragma unroll
        for (int j = 0; j < 8; j++) s += partial[tid][j];
        fsc[tid] = s;
    }
    __syncthreads();

    // warp 0: exact top-11 of 32
    if (tid < 32) {
        float v = fsc[tid];
        int ix = sel_ix[tid];
        size_t ob = ((size_t)sp * Q_ + q) * NB;
        for (int r = 0; r < NB; r++) {
            float bv = v; int bl = tid;
            #pragma unroll
            for (int off = 16; off > 0; off >>= 1) {
                float ov = __shfl_down_sync(0xffffffffu, bv, off);
                int   ol = __shfl_down_sync(0xffffffffu, bl, off);
                if (ov > bv) { bv = ov; bl = ol; }
            }
            bl = __shfl_sync(0xffffffffu, bl, 0);
            float wv = __shfl_sync(0xffffffffu, v, bl);
            int   wi = __shfl_sync(0xffffffffu, ix, bl);
            if (tid == 0) { g_best_sc[ob + r] = wv; g_best_ix[ob + r] = wi; }
            if (tid == bl) v = NEG_INF;
            __syncwarp();
        }
    }
}

// ============================================================
// Kernel 3: per (s,b) merge 4 x 11 -> top-10; write output
// ============================================================
__global__ void final_kernel(float* __restrict__ out) {
    int q = blockIdx.x * blockDim.x + threadIdx.x;
    if (q >= Q_) return;
    float bs[KOUT]; int bg[KOUT];
    #pragma unroll
    for (int r = 0; r < KOUT; r++) { bs[r] = NEG_INF; bg[r] = -1; }
    for (int sp = 0; sp < S_; sp++) {
        size_t base = ((size_t)sp * Q_ + q) * NB;
        for (int r = 0; r < NB; r++) {
            float v = g_best_sc[base + r];
            if (v > bs[KOUT - 1]) {
                int gid = g_best_ix[base + r] * S_ + sp;
                float cv = v; int ci = gid;
                #pragma unroll
                for (int k = 0; k < KOUT; k++) {
                    if (cv > bs[k]) {
                        float t0 = bs[k]; int t1 = bg[k];
                        bs[k] = cv; bg[k] = ci; cv = t0; ci = t1;
                    }
                }
            }
        }
    }
    #pragma unroll
    for (int k = 0; k < KOUT; k++) {
        out[q * KOUT + k]             = (float)bg[k];
        out[Q_ * KOUT + q * KOUT + k] = bs[k];
    }
}

// ============================================================
extern "C" void kernel_launch(void* const* d_in, const int* in_sizes, int n_in,
                              void* d_out, int out_size) {
    const int*   relation = (const int*)d_in[0];
    const int*   head     = (const int*)d_in[1];
    const float* ent      = (const float*)d_in[2];
    const float* rel      = (const float*)d_in[3];
    float* out = (float*)d_out;

    cudaFuncSetAttribute(score_kernel, cudaFuncAttributeMaxDynamicSharedMemorySize, SM_TOTAL);

    conv_kernel<<<(int)(((size_t)S_ * P_ * D_ / 4) / 256), 256>>>(ent);
    qvec_kernel<<<Q_, D_>>>(relation, head, ent, rel);
    dim3 g1(NQT, NPT, S_);
    score_kernel<<<g1, 512, SM_TOTAL>>>();
    select_kernel<<<S_ * Q_, 256>>>(ent);
    final_kernel<<<4, 256>>>(out);
}

// round 7
// speedup vs baseline: 1.3739x; 1.2948x over previous
#include <cuda_runtime.h>
#include <cuda_fp16.h>
#include <cstdint>

#define S_   4
#define B_   256
#define Q_   1024
#define P_   32768
#define D_   256
#define NB   11
#define KOUT 10
#define NEG_INF (-1e30f)

#define PT    256           // p per score tile
#define NPT   128           // P_/PT
#define QT    128           // q per score tile
#define NQT   8             // Q_/QT
#define TOPT  8             // candidates kept per (q, ptile)
#define MSEL  48            // candidates rescored per (s',q)

// ---------------- static device scratch ----------------
__device__ float  g_qvec [Q_ * D_];
__device__ __half g_qvech[Q_ * D_];
__device__ __half g_enth [(size_t)S_ * P_ * D_];                 // 64MB
__device__ float  g_cand_sc[(size_t)S_ * Q_ * NPT * TOPT];       // 16MB
__device__ int    g_cand_ix[(size_t)S_ * Q_ * NPT * TOPT];       // 16MB
__device__ float  g_best_sc[S_ * Q_ * NB];
__device__ int    g_best_ix[S_ * Q_ * NB];

__device__ __forceinline__ uint32_t smem_to_u32(const void* p) {
    uint32_t a;
    asm("{ .reg .u64 t; cvta.to.shared.u64 t, %1; cvt.u32.u64 %0, t; }" : "=r"(a) : "l"(p));
    return a;
}
// 16B-chunk XOR swizzle within a 512B row (32 chunks): conflict-free ldmatrix
__device__ __forceinline__ uint32_t swz(int row, int chunk) {
    int c = (chunk & ~7) | ((chunk ^ row) & 7);
    return (uint32_t)(row * 512 + c * 16);
}
__device__ __forceinline__ void cp_async16(uint32_t smem, const void* gmem) {
    asm volatile("cp.async.cg.shared.global [%0], [%1], 16;" :: "r"(smem), "l"(gmem));
}
__device__ __forceinline__ void cp_commit_wait() {
    asm volatile("cp.async.commit_group;");
    asm volatile("cp.async.wait_group 0;");
}
__device__ __forceinline__ void ldsm_x4(uint32_t* r, uint32_t addr) {
    asm volatile("ldmatrix.sync.aligned.m8n8.x4.shared.b16 {%0,%1,%2,%3}, [%4];"
                 : "=r"(r[0]), "=r"(r[1]), "=r"(r[2]), "=r"(r[3]) : "r"(addr));
}
__device__ __forceinline__ void ldsm_x2(uint32_t* r, uint32_t addr) {
    asm volatile("ldmatrix.sync.aligned.m8n8.x2.shared.b16 {%0,%1}, [%2];"
                 : "=r"(r[0]), "=r"(r[1]) : "r"(addr));
}
// f16 inputs, f16 accumulation
__device__ __forceinline__ void mma16816_f16(uint32_t* d, const uint32_t* a, const uint32_t* b) {
    asm volatile(
        "mma.sync.aligned.m16n8k16.row.col.f16.f16.f16.f16 "
        "{%0,%1}, {%2,%3,%4,%5}, {%6,%7}, {%0,%1};"
        : "+r"(d[0]), "+r"(d[1])
        : "r"(a[0]), "r"(a[1]), "r"(a[2]), "r"(a[3]), "r"(b[0]), "r"(b[1]));
}

// ============================================================
// Kernel 0a: ent f32 -> f16
// ============================================================
__global__ void conv_kernel(const float* __restrict__ ent) {
    size_t i = ((size_t)blockIdx.x * blockDim.x + threadIdx.x) * 4;
    float4 v = *(const float4*)(ent + i);
    *(__half2*)(g_enth + i)     = __floats2half2_rn(v.x, v.y);
    *(__half2*)(g_enth + i + 2) = __floats2half2_rn(v.z, v.w);
}

// ============================================================
// Kernel 0b: qvec f32 + f16
// ============================================================
__global__ void qvec_kernel(const int* __restrict__ relation,
                            const int* __restrict__ head,
                            const float* __restrict__ ent,
                            const float* __restrict__ rel) {
    int q = blockIdx.x, d = threadIdx.x;
    int s = q >> 8;
    int hd = head[q], rr = relation[q];
    float v = ent[((size_t)s * P_ + hd) * D_ + d] * rel[(size_t)rr * D_ + d];
    g_qvec[q * D_ + d]  = v;
    g_qvech[q * D_ + d] = __float2half_rn(v);
}

// ============================================================
// Kernel 1: HMMA f16 score + per-(q,ptile) top-8
// grid (8, 128, 4), block 512 (16 warps; warp tile 64q x 32p)
// mainloop smem: A f16 [128][256] @0 (64KB), B @65536 (128KB)
// epilogue overlay: sSh u32(f16x2) [128][132] @0 (67584B),
//   scr_sc f32 @98304 (16KB), scr_ix @114688 (16KB)
// ============================================================
#define SM_B_OFF   65536
#define SM_SH_STR  132
#define SM_SCR_SC  98304
#define SM_SCR_IX  114688
#define SM_TOTAL   196608

__global__ __launch_bounds__(512) void score_kernel() {
    extern __shared__ char sm[];
    const uint32_t sbase = smem_to_u32(sm);
    const int tid = threadIdx.x;
    const int wid = tid >> 5, lane = tid & 31;
    const int qtile = blockIdx.x, ptile = blockIdx.y, sp = blockIdx.z;

    // ---- stage A: 128 rows x 256 f16 ----
    {
        const __half* src = g_qvech + (size_t)qtile * QT * D_;
        #pragma unroll
        for (int it = 0; it < 8; it++) {
            int i = tid + it * 512;
            int row = i >> 5, ch = i & 31;
            cp_async16(sbase + swz(row, ch), src + (size_t)row * D_ + ch * 8);
        }
    }
    // ---- stage B: 256 rows x 256 f16 ----
    {
        const __half* src = g_enth + ((size_t)sp * P_ + (size_t)ptile * PT) * D_;
        #pragma unroll
        for (int it = 0; it < 16; it++) {
            int i = tid + it * 512;
            int row = i >> 5, ch = i & 31;
            cp_async16(sbase + SM_B_OFF + swz(row, ch), src + (size_t)row * D_ + ch * 8);
        }
    }
    cp_commit_wait();
    __syncthreads();

    // ---- MMA main loop: warp tile 64q x 32p, f16 accum ----
    const int wq = wid >> 3;
    const int wp = wid & 7;
    const int q0 = wq * 64, p0 = wp * 32;

    uint32_t d[4][4][2];
    #pragma unroll
    for (int mi = 0; mi < 4; mi++)
        #pragma unroll
        for (int ni = 0; ni < 4; ni++) { d[mi][ni][0] = 0u; d[mi][ni][1] = 0u; }

    const int arow = (lane & 15);
    const int asel = (lane >> 4);
    const int brow = (lane & 7);
    const int bsel = ((lane >> 3) & 1);

    #pragma unroll
    for (int ks = 0; ks < 16; ks++) {
        const int ch0 = ks * 2;
        uint32_t a[4][4], b[4][2];
        #pragma unroll
        for (int mi = 0; mi < 4; mi++)
            ldsm_x4(a[mi], sbase + swz(q0 + mi * 16 + arow, ch0 + asel));
        #pragma unroll
        for (int ni = 0; ni < 4; ni++)
            ldsm_x2(b[ni], sbase + SM_B_OFF + swz(p0 + ni * 8 + brow, ch0 + bsel));
        #pragma unroll
        for (int mi = 0; mi < 4; mi++)
            #pragma unroll
            for (int ni = 0; ni < 4; ni++)
                mma16816_f16(d[mi][ni], a[mi], b[ni]);
    }
    __syncthreads();   // staged tiles dead; epilogue overlays them

    // ---- dump raw f16x2 accum words -> sSh [128][132] (u32) ----
    uint32_t* sSh = (uint32_t*)sm;
    {
        int rr = lane >> 2, cc = 2 * (lane & 3);
        #pragma unroll
        for (int mi = 0; mi < 4; mi++)
            #pragma unroll
            for (int ni = 0; ni < 4; ni++) {
                int r  = q0 + mi * 16 + rr;
                int pr = (p0 + ni * 8 + cc) >> 1;     // pair index 0..127
                sSh[r * SM_SH_STR + pr]       = d[mi][ni][0];  // rows r
                sSh[(r + 8) * SM_SH_STR + pr] = d[mi][ni][1];  // rows r+8
            }
    }
    __syncthreads();

    // ---- per-thread top-8 over 64 p's (32 f16x2 words, interleaved) ----
    float* scr_sc = (float*)(sm + SM_SCR_SC);
    int*   scr_ix = (int*)(sm + SM_SCR_IX);
    const int tq = tid >> 2, tsg = tid & 3;
    const int pg0 = ptile * PT;
    {
        float bs[TOPT]; int bi[TOPT];
        #pragma unroll
        for (int r = 0; r < TOPT; r++) { bs[r] = NEG_INF; bi[r] = 0; }
        #pragma unroll 8
        for (int i = 0; i < 32; i++) {
            int p2 = tsg + (i << 2);
            uint32_t u = sSh[tq * SM_SH_STR + p2];
            float2 f = __half22float2(*(__half2*)&u);
            #pragma unroll
            for (int h = 0; h < 2; h++) {
                float v = h ? f.y : f.x;
                if (v > bs[TOPT - 1]) {
                    float cv = v; int ci = pg0 + 2 * p2 + h;
                    #pragma unroll
                    for (int r = 0; r < TOPT; r++) {
                        if (cv > bs[r]) {
                            float t0 = bs[r]; int t1 = bi[r];
                            bs[r] = cv; bi[r] = ci; cv = t0; ci = t1;
                        }
                    }
                }
            }
        }
        #pragma unroll
        for (int r = 0; r < TOPT; r++) {
            scr_sc[(tq * 4 + tsg) * TOPT + r] = bs[r];
            scr_ix[(tq * 4 + tsg) * TOPT + r] = bi[r];
        }
    }
    __syncthreads();

    // ---- leader: merge 4 sorted top-8 lists -> sorted top-8, write ----
    if (tsg == 0) {
        int q = qtile * QT + tq;
        size_t ob = (((size_t)sp * Q_ + q) * NPT + ptile) * TOPT;
        int h0 = 0, h1 = 0, h2 = 0, h3 = 0;
        const float* L = scr_sc + (size_t)tq * 4 * TOPT;
        const int*   X = scr_ix + (size_t)tq * 4 * TOPT;
        #pragma unroll
        for (int r = 0; r < TOPT; r++) {
            float best = NEG_INF; int bj = 0, bh = 0;
            #define TRYM(j, h) { float v = ((h) < TOPT) ? L[(j) * TOPT + (h)] : NEG_INF; \
                                 if (v > best) { best = v; bj = (j); bh = (h); } }
            TRYM(0, h0) TRYM(1, h1) TRYM(2, h2) TRYM(3, h3)
            #undef TRYM
            g_cand_sc[ob + r] = best;
            g_cand_ix[ob + r] = X[bj * TOPT + bh];
            if      (bj == 0) h0++;
            else if (bj == 1) h1++;
            else if (bj == 2) h2++;
            else              h3++;
        }
    }
}

// ============================================================
// Kernel 2: per (s',q): tournament over 128 sorted top-8 lists
// -> approx top-48, exact f32 rescore, exact top-11.
// grid 4096, block 384
// ============================================================
__global__ __launch_bounds__(384) void select_kernel(const float* __restrict__ ent) {
    __shared__ float cs_t[TOPT][NPT];      // [rank][list]
    __shared__ int   ci_t[TOPT][NPT];
    __shared__ int   sel_ix[MSEL];
    __shared__ float partial[MSEL][8];
    __shared__ float fsc[MSEL];

    const int tid = threadIdx.x;
    const int pair = blockIdx.x;
    const int sp = pair >> 10, q = pair & 1023;
    size_t base = ((size_t)sp * Q_ + q) * (size_t)(NPT * TOPT);

    for (int e = tid; e < NPT * TOPT; e += 384) {
        cs_t[e & 7][e >> 3] = g_cand_sc[base + e];
        ci_t[e & 7][e >> 3] = g_cand_ix[base + e];
    }
    __syncthreads();

    // warp 0: tournament; lane owns 4 lists with register heads
    if (tid < 32) {
        int   h[4];
        float hv[4];
        #pragma unroll
        for (int j = 0; j < 4; j++) { h[j] = 0; hv[j] = cs_t[0][tid * 4 + j]; }
        for (int r = 0; r < MSEL; r++) {
            float best = hv[0]; int bj = 0;
            #pragma unroll
            for (int j = 1; j < 4; j++) if (hv[j] > best) { best = hv[j]; bj = j; }
            float bv = best; int bl = tid;
            #pragma unroll
            for (int off = 16; off > 0; off >>= 1) {
                float ov = __shfl_down_sync(0xffffffffu, bv, off);
                int   ol = __shfl_down_sync(0xffffffffu, bl, off);
                if (ov > bv) { bv = ov; bl = ol; }
            }
            bl = __shfl_sync(0xffffffffu, bl, 0);
            if (tid == bl) {
                int list = tid * 4 + bj;
                sel_ix[r] = ci_t[h[bj]][list];
                h[bj]++;
                hv[bj] = (h[bj] < TOPT) ? cs_t[h[bj]][list] : NEG_INF;
            }
            __syncwarp();
        }
    }
    __syncthreads();

    // exact f32 rescore: 8 threads per candidate, 48 candidates
    {
        int c = tid >> 3, part = tid & 7;
        int p = sel_ix[c];
        const float4* qv = (const float4*)(g_qvec + (size_t)q * D_ + part * 32);
        const float4* ev = (const float4*)(ent + ((size_t)sp * P_ + p) * D_ + part * 32);
        float accv = 0.f;
        #pragma unroll
        for (int i = 0; i < 8; i++) {
            float4 a = qv[i], e = ev[i];
            accv = fmaf(a.x, e.x, fmaf(a.y, e.y, fmaf(a.z, e.z, fmaf(a.w, e.w, accv))));
        }
        partial[c][part] = accv;
    }
    __syncthreads();
    if (tid < MSEL) {
        float s = 0.f;
        #pragma unroll
        for (int j = 0; j < 8; j++) s += partial[tid][j];
        fsc[tid] = s;
    }
    __syncthreads();

    // warp 0: exact top-11 of 48 (2 values per lane)
    if (tid < 32) {
        float v0 = fsc[tid];
        float v1 = (tid + 32 < MSEL) ? fsc[tid + 32] : NEG_INF;
        int   x0 = sel_ix[tid];
        int   x1 = (tid + 32 < MSEL) ? sel_ix[tid + 32] : 0;
        size_t ob = ((size_t)sp * Q_ + q) * NB;
        for (int r = 0; r < NB; r++) {
            float lv = v0; int lsel = 0;
            if (v1 > lv) { lv = v1; lsel = 1; }
            float bv = lv; int bl = tid;
            #pragma unroll
            for (int off = 16; off > 0; off >>= 1) {
                float ov = __shfl_down_sync(0xffffffffu, bv, off);
                int   ol = __shfl_down_sync(0xffffffffu, bl, off);
                if (ov > bv) { bv = ov; bl = ol; }
            }
            bl = __shfl_sync(0xffffffffu, bl, 0);
            int lx = lsel ? x1 : x0;
            float wv = __shfl_sync(0xffffffffu, lv, bl);
            int   wx = __shfl_sync(0xffffffffu, lx, bl);
            if (tid == 0) { g_best_sc[ob + r] = wv; g_best_ix[ob + r] = wx; }
            if (tid == bl) { if (lsel) v1 = NEG_INF; else v0 = NEG_INF; }
            __syncwarp();
        }
    }
}

// ============================================================
// Kernel 3: per (s,b) merge 4 x 11 -> top-10; write output
// ============================================================
__global__ void final_kernel(float* __restrict__ out) {
    int q = blockIdx.x * blockDim.x + threadIdx.x;
    if (q >= Q_) return;
    float bs[KOUT]; int bg[KOUT];
    #pragma unroll
    for (int r = 0; r < KOUT; r++) { bs[r] = NEG_INF; bg[r] = -1; }
    for (int sp = 0; sp < S_; sp++) {
        size_t base = ((size_t)sp * Q_ + q) * NB;
        for (int r = 0; r < NB; r++) {
            float v = g_best_sc[base + r];
            if (v > bs[KOUT - 1]) {
                int gid = g_best_ix[base + r] * S_ + sp;
                float cv = v; int ci = gid;
                #pragma unroll
                for (int k = 0; k < KOUT; k++) {
                    if (cv > bs[k]) {
                        float t0 = bs[k]; int t1 = bg[k];
                        bs[k] = cv; bg[k] = ci; cv = t0; ci = t1;
                    }
                }
            }
        }
    }
    #pragma unroll
    for (int k = 0; k < KOUT; k++) {
        out[q * KOUT + k]             = (float)bg[k];
        out[Q_ * KOUT + q * KOUT + k] = bs[k];
    }
}

// ============================================================
extern "C" void kernel_launch(void* const* d_in, const int* in_sizes, int n_in,
                              void* d_out, int out_size) {
    const int*   relation = (const int*)d_in[0];
    const int*   head     = (const int*)d_in[1];
    const float* ent      = (const float*)d_in[2];
    const float* rel      = (const float*)d_in[3];
    float* out = (float*)d_out;

    cudaFuncSetAttribute(score_kernel, cudaFuncAttributeMaxDynamicSharedMemorySize, SM_TOTAL);

    conv_kernel<<<(int)(((size_t)S_ * P_ * D_ / 4) / 256), 256>>>(ent);
    qvec_kernel<<<Q_, D_>>>(relation, head, ent, rel);
    dim3 g1(NQT, NPT, S_);
    score_kernel<<<g1, 512, SM_TOTAL>>>();
    select_kernel<<<S_ * Q_, 384>>>(ent);
    final_kernel<<<4, 256>>>(out);
}

// round 8
// speedup vs baseline: 1.4881x; 1.0831x over previous
#include <cuda_runtime.h>
#include <cuda_fp16.h>
#include <cstdint>

#define S_   4
#define B_   256
#define Q_   1024
#define P_   32768
#define D_   256
#define NB   11
#define KOUT 10
#define NEG_INF (-1e30f)

#define PT    256           // p per score tile
#define NPT   128           // P_/NPT
#define QT    128           // q per score tile
#define NQT   8             // Q_/QT
#define TOPT  8             // candidates kept per (q, ptile)
#define MSEL  32            // candidates rescored per (s',q)

// ---------------- static device scratch ----------------
__device__ float  g_qvec [Q_ * D_];
__device__ __half g_qvech[Q_ * D_];
__device__ __half g_enth [(size_t)S_ * P_ * D_];                 // 64MB
__device__ float  g_cand_sc[(size_t)S_ * Q_ * NPT * TOPT];       // 16MB
__device__ int    g_cand_ix[(size_t)S_ * Q_ * NPT * TOPT];       // 16MB
__device__ float  g_best_sc[S_ * Q_ * NB];
__device__ int    g_best_ix[S_ * Q_ * NB];

__device__ __forceinline__ uint32_t smem_to_u32(const void* p) {
    uint32_t a;
    asm("{ .reg .u64 t; cvta.to.shared.u64 t, %1; cvt.u32.u64 %0, t; }" : "=r"(a) : "l"(p));
    return a;
}
// 16B-chunk XOR swizzle within a 512B row (32 chunks): conflict-free ldmatrix
__device__ __forceinline__ uint32_t swz(int row, int chunk) {
    int c = (chunk & ~7) | ((chunk ^ row) & 7);
    return (uint32_t)(row * 512 + c * 16);
}
__device__ __forceinline__ void cp_async16(uint32_t smem, const void* gmem) {
    asm volatile("cp.async.cg.shared.global [%0], [%1], 16;" :: "r"(smem), "l"(gmem));
}
__device__ __forceinline__ void cp_commit_wait() {
    asm volatile("cp.async.commit_group;");
    asm volatile("cp.async.wait_group 0;");
}
__device__ __forceinline__ void ldsm_x4(uint32_t* r, uint32_t addr) {
    asm volatile("ldmatrix.sync.aligned.m8n8.x4.shared.b16 {%0,%1,%2,%3}, [%4];"
                 : "=r"(r[0]), "=r"(r[1]), "=r"(r[2]), "=r"(r[3]) : "r"(addr));
}
__device__ __forceinline__ void ldsm_x2(uint32_t* r, uint32_t addr) {
    asm volatile("ldmatrix.sync.aligned.m8n8.x2.shared.b16 {%0,%1}, [%2];"
                 : "=r"(r[0]), "=r"(r[1]) : "r"(addr));
}
// f16 inputs, f16 accumulation
__device__ __forceinline__ void mma16816_f16(uint32_t* d, const uint32_t* a, const uint32_t* b) {
    asm volatile(
        "mma.sync.aligned.m16n8k16.row.col.f16.f16.f16.f16 "
        "{%0,%1}, {%2,%3,%4,%5}, {%6,%7}, {%0,%1};"
        : "+r"(d[0]), "+r"(d[1])
        : "r"(a[0]), "r"(a[1]), "r"(a[2]), "r"(a[3]), "r"(b[0]), "r"(b[1]));
}

// ============================================================
// Kernel 0a: ent f32 -> f16
// ============================================================
__global__ void conv_kernel(const float* __restrict__ ent) {
    size_t i = ((size_t)blockIdx.x * blockDim.x + threadIdx.x) * 4;
    float4 v = *(const float4*)(ent + i);
    *(__half2*)(g_enth + i)     = __floats2half2_rn(v.x, v.y);
    *(__half2*)(g_enth + i + 2) = __floats2half2_rn(v.z, v.w);
}

// ============================================================
// Kernel 0b: qvec f32 + f16
// ============================================================
__global__ void qvec_kernel(const int* __restrict__ relation,
                            const int* __restrict__ head,
                            const float* __restrict__ ent,
                            const float* __restrict__ rel) {
    int q = blockIdx.x, d = threadIdx.x;
    int s = q >> 8;
    int hd = head[q], rr = relation[q];
    float v = ent[((size_t)s * P_ + hd) * D_ + d] * rel[(size_t)rr * D_ + d];
    g_qvec[q * D_ + d]  = v;
    g_qvech[q * D_ + d] = __float2half_rn(v);
}

// ============================================================
// Kernel 1: HMMA f16 score + per-(q,ptile) top-8
// grid (8, 128, 4), block 512 (16 warps; warp tile 64q x 32p)
// mainloop smem: A f16 [128][256] @0 (64KB), B @65536 (128KB)
// epilogue overlay: sSh u32(f16x2) [128][132] @0 (67584B),
//   scr_sc f32 @98304 (16KB), scr_ix @114688 (16KB)
// ============================================================
#define SM_B_OFF   65536
#define SM_SH_STR  132
#define SM_SCR_SC  98304
#define SM_SCR_IX  114688
#define SM_TOTAL   196608

__global__ __launch_bounds__(512) void score_kernel() {
    extern __shared__ char sm[];
    const uint32_t sbase = smem_to_u32(sm);
    const int tid = threadIdx.x;
    const int wid = tid >> 5, lane = tid & 31;
    const int qtile = blockIdx.x, ptile = blockIdx.y, sp = blockIdx.z;

    // ---- stage A: 128 rows x 256 f16 ----
    {
        const __half* src = g_qvech + (size_t)qtile * QT * D_;
        #pragma unroll
        for (int it = 0; it < 8; it++) {
            int i = tid + it * 512;
            int row = i >> 5, ch = i & 31;
            cp_async16(sbase + swz(row, ch), src + (size_t)row * D_ + ch * 8);
        }
    }
    // ---- stage B: 256 rows x 256 f16 ----
    {
        const __half* src = g_enth + ((size_t)sp * P_ + (size_t)ptile * PT) * D_;
        #pragma unroll
        for (int it = 0; it < 16; it++) {
            int i = tid + it * 512;
            int row = i >> 5, ch = i & 31;
            cp_async16(sbase + SM_B_OFF + swz(row, ch), src + (size_t)row * D_ + ch * 8);
        }
    }
    cp_commit_wait();
    __syncthreads();

    // ---- MMA main loop: warp tile 64q x 32p, f16 accum ----
    const int wq = wid >> 3;
    const int wp = wid & 7;
    const int q0 = wq * 64, p0 = wp * 32;

    uint32_t d[4][4][2];
    #pragma unroll
    for (int mi = 0; mi < 4; mi++)
        #pragma unroll
        for (int ni = 0; ni < 4; ni++) { d[mi][ni][0] = 0u; d[mi][ni][1] = 0u; }

    const int arow = (lane & 15);
    const int asel = (lane >> 4);
    const int brow = (lane & 7);
    const int bsel = ((lane >> 3) & 1);

    #pragma unroll
    for (int ks = 0; ks < 16; ks++) {
        const int ch0 = ks * 2;
        uint32_t a[4][4], b[4][2];
        #pragma unroll
        for (int mi = 0; mi < 4; mi++)
            ldsm_x4(a[mi], sbase + swz(q0 + mi * 16 + arow, ch0 + asel));
        #pragma unroll
        for (int ni = 0; ni < 4; ni++)
            ldsm_x2(b[ni], sbase + SM_B_OFF + swz(p0 + ni * 8 + brow, ch0 + bsel));
        #pragma unroll
        for (int mi = 0; mi < 4; mi++)
            #pragma unroll
            for (int ni = 0; ni < 4; ni++)
                mma16816_f16(d[mi][ni], a[mi], b[ni]);
    }
    __syncthreads();   // staged tiles dead; epilogue overlays them

    // ---- dump raw f16x2 accum words -> sSh [128][132] (u32) ----
    uint32_t* sSh = (uint32_t*)sm;
    {
        int rr = lane >> 2, cc = 2 * (lane & 3);
        #pragma unroll
        for (int mi = 0; mi < 4; mi++)
            #pragma unroll
            for (int ni = 0; ni < 4; ni++) {
                int r  = q0 + mi * 16 + rr;
                int pr = (p0 + ni * 8 + cc) >> 1;     // pair index 0..127
                sSh[r * SM_SH_STR + pr]       = d[mi][ni][0];  // rows r
                sSh[(r + 8) * SM_SH_STR + pr] = d[mi][ni][1];  // rows r+8
            }
    }
    __syncthreads();

    // ---- per-thread top-8 over 64 p's (32 f16x2 words, interleaved) ----
    float* scr_sc = (float*)(sm + SM_SCR_SC);
    int*   scr_ix = (int*)(sm + SM_SCR_IX);
    const int tq = tid >> 2, tsg = tid & 3;
    const int pg0 = ptile * PT;
    {
        float bs[TOPT]; int bi[TOPT];
        #pragma unroll
        for (int r = 0; r < TOPT; r++) { bs[r] = NEG_INF; bi[r] = 0; }
        #pragma unroll 8
        for (int i = 0; i < 32; i++) {
            int p2 = tsg + (i << 2);
            uint32_t u = sSh[tq * SM_SH_STR + p2];
            float2 f = __half22float2(*(__half2*)&u);
            #pragma unroll
            for (int h = 0; h < 2; h++) {
                float v = h ? f.y : f.x;
                if (v > bs[TOPT - 1]) {
                    float cv = v; int ci = pg0 + 2 * p2 + h;
                    #pragma unroll
                    for (int r = 0; r < TOPT; r++) {
                        if (cv > bs[r]) {
                            float t0 = bs[r]; int t1 = bi[r];
                            bs[r] = cv; bi[r] = ci; cv = t0; ci = t1;
                        }
                    }
                }
            }
        }
        #pragma unroll
        for (int r = 0; r < TOPT; r++) {
            scr_sc[(tq * 4 + tsg) * TOPT + r] = bs[r];
            scr_ix[(tq * 4 + tsg) * TOPT + r] = bi[r];
        }
    }
    __syncthreads();

    // ---- leader: merge 4 sorted top-8 lists -> sorted top-8, write ----
    if (tsg == 0) {
        int q = qtile * QT + tq;
        size_t ob = (((size_t)sp * Q_ + q) * NPT + ptile) * TOPT;
        int h0 = 0, h1 = 0, h2 = 0, h3 = 0;
        const float* L = scr_sc + (size_t)tq * 4 * TOPT;
        const int*   X = scr_ix + (size_t)tq * 4 * TOPT;
        #pragma unroll
        for (int r = 0; r < TOPT; r++) {
            float best = NEG_INF; int bj = 0, bh = 0;
            #define TRYM(j, h) { float v = ((h) < TOPT) ? L[(j) * TOPT + (h)] : NEG_INF; \
                                 if (v > best) { best = v; bj = (j); bh = (h); } }
            TRYM(0, h0) TRYM(1, h1) TRYM(2, h2) TRYM(3, h3)
            #undef TRYM
            g_cand_sc[ob + r] = best;
            g_cand_ix[ob + r] = X[bj * TOPT + bh];
            if      (bj == 0) h0++;
            else if (bj == 1) h1++;
            else if (bj == 2) h2++;
            else              h3++;
        }
    }
}

// ============================================================
// Kernel 2: per (s',q): tournament over 128 sorted top-8 lists
// -> approx top-32, exact f32 rescore, exact top-11.
// grid 4096, block 256
// ============================================================
__global__ __launch_bounds__(256) void select_kernel(const float* __restrict__ ent) {
    __shared__ float cs_t[TOPT][NPT];      // [rank][list]
    __shared__ int   ci_t[TOPT][NPT];
    __shared__ int   sel_ix[MSEL];
    __shared__ float partial[MSEL][8];
    __shared__ float fsc[MSEL];

    const int tid = threadIdx.x;
    const int pair = blockIdx.x;
    const int sp = pair >> 10, q = pair & 1023;
    size_t base = ((size_t)sp * Q_ + q) * (size_t)(NPT * TOPT);

    for (int e = tid; e < NPT * TOPT; e += 256) {
        cs_t[e & 7][e >> 3] = g_cand_sc[base + e];
        ci_t[e & 7][e >> 3] = g_cand_ix[base + e];
    }
    __syncthreads();

    // warp 0: tournament; lane owns 4 lists with register heads
    if (tid < 32) {
        int   h[4];
        float hv[4];
        #pragma unroll
        for (int j = 0; j < 4; j++) { h[j] = 0; hv[j] = cs_t[0][tid * 4 + j]; }
        for (int r = 0; r < MSEL; r++) {
            float best = hv[0]; int bj = 0;
            #pragma unroll
            for (int j = 1; j < 4; j++) if (hv[j] > best) { best = hv[j]; bj = j; }
            float bv = best; int bl = tid;
            #pragma unroll
            for (int off = 16; off > 0; off >>= 1) {
                float ov = __shfl_down_sync(0xffffffffu, bv, off);
                int   ol = __shfl_down_sync(0xffffffffu, bl, off);
                if (ov > bv) { bv = ov; bl = ol; }
            }
            bl = __shfl_sync(0xffffffffu, bl, 0);
            if (tid == bl) {
                int list = tid * 4 + bj;
                sel_ix[r] = ci_t[h[bj]][list];
                h[bj]++;
                hv[bj] = (h[bj] < TOPT) ? cs_t[h[bj]][list] : NEG_INF;
            }
            __syncwarp();
        }
    }
    __syncthreads();

    // exact f32 rescore: 8 threads per candidate, 32 candidates
    {
        int c = tid >> 3, part = tid & 7;
        int p = sel_ix[c];
        const float4* qv = (const float4*)(g_qvec + (size_t)q * D_ + part * 32);
        const float4* ev = (const float4*)(ent + ((size_t)sp * P_ + p) * D_ + part * 32);
        float accv = 0.f;
        #pragma unroll
        for (int i = 0; i < 8; i++) {
            float4 a = qv[i], e = ev[i];
            accv = fmaf(a.x, e.x, fmaf(a.y, e.y, fmaf(a.z, e.z, fmaf(a.w, e.w, accv))));
        }
        partial[c][part] = accv;
    }
    __syncthreads();
    if (tid < MSEL) {
        float s = 0.f;
        #pragma unroll
        for (int j = 0; j < 8; j++) s += partial[tid][j];
        fsc[tid] = s;
    }
    __syncthreads();

    // warp 0: exact top-11 of 32
    if (tid < 32) {
        float v = fsc[tid];
        int ix = sel_ix[tid];
        size_t ob = ((size_t)sp * Q_ + q) * NB;
        for (int r = 0; r < NB; r++) {
            float bv = v; int bl = tid;
            #pragma unroll
            for (int off = 16; off > 0; off >>= 1) {
                float ov = __shfl_down_sync(0xffffffffu, bv, off);
                int   ol = __shfl_down_sync(0xffffffffu, bl, off);
                if (ov > bv) { bv = ov; bl = ol; }
            }
            bl = __shfl_sync(0xffffffffu, bl, 0);
            float wv = __shfl_sync(0xffffffffu, v, bl);
            int   wi = __shfl_sync(0xffffffffu, ix, bl);
            if (tid == 0) { g_best_sc[ob + r] = wv; g_best_ix[ob + r] = wi; }
            if (tid == bl) v = NEG_INF;
            __syncwarp();
        }
    }
}

// ============================================================
// Kernel 3: per (s,b) merge 4 x 11 -> top-10; write output
// ============================================================
__global__ void final_kernel(float* __restrict__ out) {
    int q = blockIdx.x * blockDim.x + threadIdx.x;
    if (q >= Q_) return;
    float bs[KOUT]; int bg[KOUT];
    #pragma unroll
    for (int r = 0; r < KOUT; r++) { bs[r] = NEG_INF; bg[r] = -1; }
    for (int sp = 0; sp < S_; sp++) {
        size_t base = ((size_t)sp * Q_ + q) * NB;
        for (int r = 0; r < NB; r++) {
            float v = g_best_sc[base + r];
            if (v > bs[KOUT - 1]) {
                int gid = g_best_ix[base + r] * S_ + sp;
                float cv = v; int ci = gid;
                #pragma unroll
                for (int k = 0; k < KOUT; k++) {
                    if (cv > bs[k]) {
                        float t0 = bs[k]; int t1 = bg[k];
                        bs[k] = cv; bg[k] = ci; cv = t0; ci = t1;
                    }
                }
            }
        }
    }
    #pragma unroll
    for (int k = 0; k < KOUT; k++) {
        out[q * KOUT + k]             = (float)bg[k];
        out[Q_ * KOUT + q * KOUT + k] = bs[k];
    }
}

// ============================================================
extern "C" void kernel_launch(void* const* d_in, const int* in_sizes, int n_in,
                              void* d_out, int out_size) {
    const int*   relation = (const int*)d_in[0];
    const int*   head     = (const int*)d_in[1];
    const float* ent      = (const float*)d_in[2];
    const float* rel      = (const float*)d_in[3];
    float* out = (float*)d_out;

    cudaFuncSetAttribute(score_kernel, cudaFuncAttributeMaxDynamicSharedMemorySize, SM_TOTAL);

    conv_kernel<<<(int)(((size_t)S_ * P_ * D_ / 4) / 256), 256>>>(ent);
    qvec_kernel<<<Q_, D_>>>(relation, head, ent, rel);
    dim3 g1(NQT, NPT, S_);
    score_kernel<<<g1, 512, SM_TOTAL>>>();
    select_kernel<<<S_ * Q_, 256>>>(ent);
    final_kernel<<<4, 256>>>(out);
}

// round 10
// speedup vs baseline: 2.0459x; 1.3749x over previous
#include <cuda_runtime.h>
#include <cuda_fp16.h>
#include <cstdint>

#define S_   4
#define B_   256
#define Q_   1024
#define P_   32768
#define D_   256
#define NB   11
#define KOUT 10
#define NEG_INF (-1e30f)

#define PT    256           // p per score tile
#define NPT   128           // P_/PT
#define QT    128           // q per score tile
#define NQT   8             // Q_/QT
#define TOPT  8             // candidates kept per (q, ptile)
#define MSEL  32            // candidates rescored per (s',q)

// ---------------- static device scratch ----------------
__device__ float    g_qvec [Q_ * D_];
__device__ __half   g_qvech[Q_ * D_];
__device__ __half   g_enth [(size_t)S_ * P_ * D_];               // 64MB
__device__ uint32_t g_cand [(size_t)S_ * Q_ * NPT * TOPT];       // 16MB packed (mono16<<16)|p
__device__ float    g_best_sc[S_ * Q_ * NB];
__device__ int      g_best_ix[S_ * Q_ * NB];

__device__ __forceinline__ uint32_t smem_to_u32(const void* p) {
    uint32_t a;
    asm("{ .reg .u64 t; cvta.to.shared.u64 t, %1; cvt.u32.u64 %0, t; }" : "=r"(a) : "l"(p));
    return a;
}
// order-preserving f16 bits -> u16 code
__device__ __forceinline__ uint32_t mono16(uint32_t h) {   // h: low 16 bits valid
    uint32_t mask = (h & 0x8000u) ? 0xFFFFu : 0x8000u;
    return (h ^ mask) & 0xFFFFu;
}
// 16B-chunk XOR swizzle within a 512B row (32 chunks): conflict-free ldmatrix
__device__ __forceinline__ uint32_t swz(int row, int chunk) {
    int c = (chunk & ~7) | ((chunk ^ row) & 7);
    return (uint32_t)(row * 512 + c * 16);
}
__device__ __forceinline__ void cp_async16(uint32_t smem, const void* gmem) {
    asm volatile("cp.async.cg.shared.global [%0], [%1], 16;" :: "r"(smem), "l"(gmem));
}
__device__ __forceinline__ void cp_commit_wait() {
    asm volatile("cp.async.commit_group;");
    asm volatile("cp.async.wait_group 0;");
}
__device__ __forceinline__ void ldsm_x4(uint32_t* r, uint32_t addr) {
    asm volatile("ldmatrix.sync.aligned.m8n8.x4.shared.b16 {%0,%1,%2,%3}, [%4];"
                 : "=r"(r[0]), "=r"(r[1]), "=r"(r[2]), "=r"(r[3]) : "r"(addr));
}
__device__ __forceinline__ void ldsm_x2(uint32_t* r, uint32_t addr) {
    asm volatile("ldmatrix.sync.aligned.m8n8.x2.shared.b16 {%0,%1}, [%2];"
                 : "=r"(r[0]), "=r"(r[1]) : "r"(addr));
}
// f16 inputs, f16 accumulation
__device__ __forceinline__ void mma16816_f16(uint32_t* d, const uint32_t* a, const uint32_t* b) {
    asm volatile(
        "mma.sync.aligned.m16n8k16.row.col.f16.f16.f16.f16 "
        "{%0,%1}, {%2,%3,%4,%5}, {%6,%7}, {%0,%1};"
        : "+r"(d[0]), "+r"(d[1])
        : "r"(a[0]), "r"(a[1]), "r"(a[2]), "r"(a[3]), "r"(b[0]), "r"(b[1]));
}

// ============================================================
// Kernel 0a: ent f32 -> f16
// ============================================================
__global__ void conv_kernel(const float* __restrict__ ent) {
    size_t i = ((size_t)blockIdx.x * blockDim.x + threadIdx.x) * 4;
    float4 v = *(const float4*)(ent + i);
    *(__half2*)(g_enth + i)     = __floats2half2_rn(v.x, v.y);
    *(__half2*)(g_enth + i + 2) = __floats2half2_rn(v.z, v.w);
}

// ============================================================
// Kernel 0b: qvec f32 + f16
// ============================================================
__global__ void qvec_kernel(const int* __restrict__ relation,
                            const int* __restrict__ head,
                            const float* __restrict__ ent,
                            const float* __restrict__ rel) {
    int q = blockIdx.x, d = threadIdx.x;
    int s = q >> 8;
    int hd = head[q], rr = relation[q];
    float v = ent[((size_t)s * P_ + hd) * D_ + d] * rel[(size_t)rr * D_ + d];
    g_qvec[q * D_ + d]  = v;
    g_qvech[q * D_ + d] = __float2half_rn(v);
}

// ============================================================
// Kernel 1: HMMA f16 score + per-(q,ptile) packed top-8
// grid (8, 128, 4), block 512 (16 warps; warp tile 64q x 32p)
// mainloop smem: A f16 [128][256] @0 (64KB), B @65536 (128KB)
// epilogue overlay: sSh u32(f16x2) [128][132] @0 (67584B),
//   scr packed u32 [512][8] @98304 (16KB)
// ============================================================
#define SM_B_OFF   65536
#define SM_SH_STR  132
#define SM_SCR     98304
#define SM_TOTAL   196608

__global__ __launch_bounds__(512) void score_kernel() {
    extern __shared__ char sm[];
    const uint32_t sbase = smem_to_u32(sm);
    const int tid = threadIdx.x;
    const int wid = tid >> 5, lane = tid & 31;
    const int qtile = blockIdx.x, ptile = blockIdx.y, sp = blockIdx.z;

    // ---- stage A: 128 rows x 256 f16 ----
    {
        const __half* src = g_qvech + (size_t)qtile * QT * D_;
        #pragma unroll
        for (int it = 0; it < 8; it++) {
            int i = tid + it * 512;
            int row = i >> 5, ch = i & 31;
            cp_async16(sbase + swz(row, ch), src + (size_t)row * D_ + ch * 8);
        }
    }
    // ---- stage B: 256 rows x 256 f16 ----
    {
        const __half* src = g_enth + ((size_t)sp * P_ + (size_t)ptile * PT) * D_;
        #pragma unroll
        for (int it = 0; it < 16; it++) {
            int i = tid + it * 512;
            int row = i >> 5, ch = i & 31;
            cp_async16(sbase + SM_B_OFF + swz(row, ch), src + (size_t)row * D_ + ch * 8);
        }
    }
    cp_commit_wait();
    __syncthreads();

    // ---- MMA main loop: warp tile 64q x 32p, f16 accum ----
    const int wq = wid >> 3;
    const int wp = wid & 7;
    const int q0 = wq * 64, p0 = wp * 32;

    uint32_t d[4][4][2];
    #pragma unroll
    for (int mi = 0; mi < 4; mi++)
        #pragma unroll
        for (int ni = 0; ni < 4; ni++) { d[mi][ni][0] = 0u; d[mi][ni][1] = 0u; }

    const int arow = (lane & 15);
    const int asel = (lane >> 4);
    const int brow = (lane & 7);
    const int bsel = ((lane >> 3) & 1);

    #pragma unroll
    for (int ks = 0; ks < 16; ks++) {
        const int ch0 = ks * 2;
        uint32_t a[4][4], b[4][2];
        #pragma unroll
        for (int mi = 0; mi < 4; mi++)
            ldsm_x4(a[mi], sbase + swz(q0 + mi * 16 + arow, ch0 + asel));
        #pragma unroll
        for (int ni = 0; ni < 4; ni++)
            ldsm_x2(b[ni], sbase + SM_B_OFF + swz(p0 + ni * 8 + brow, ch0 + bsel));
        #pragma unroll
        for (int mi = 0; mi < 4; mi++)
            #pragma unroll
            for (int ni = 0; ni < 4; ni++)
                mma16816_f16(d[mi][ni], a[mi], b[ni]);
    }
    __syncthreads();   // staged tiles dead; epilogue overlays them

    // ---- dump raw f16x2 accum words -> sSh [128][132] (u32) ----
    uint32_t* sSh = (uint32_t*)sm;
    {
        int rr = lane >> 2, cc = 2 * (lane & 3);
        #pragma unroll
        for (int mi = 0; mi < 4; mi++)
            #pragma unroll
            for (int ni = 0; ni < 4; ni++) {
                int r  = q0 + mi * 16 + rr;
                int pr = (p0 + ni * 8 + cc) >> 1;     // pair index 0..127
                sSh[r * SM_SH_STR + pr]       = d[mi][ni][0];  // rows r
                sSh[(r + 8) * SM_SH_STR + pr] = d[mi][ni][1];  // rows r+8
            }
    }
    __syncthreads();

    // ---- per-thread packed top-8 over 64 p's (32 f16x2 words) ----
    uint32_t* scr = (uint32_t*)(sm + SM_SCR);   // [512][8]
    const int tq = tid >> 2, tsg = tid & 3;
    const int pg0 = ptile * PT;
    {
        uint32_t bs[TOPT];
        #pragma unroll
        for (int r = 0; r < TOPT; r++) bs[r] = 0u;
        #pragma unroll 8
        for (int i = 0; i < 32; i++) {
            int p2 = tsg + (i << 2);
            uint32_t u = sSh[tq * SM_SH_STR + p2];
            uint32_t lo = u & 0xFFFFu, hi = u >> 16;
            uint32_t v0 = (mono16(lo) << 16) | (uint32_t)(pg0 + 2 * p2);
            uint32_t v1 = (mono16(hi) << 16) | (uint32_t)(pg0 + 2 * p2 + 1);
            #pragma unroll
            for (int h = 0; h < 2; h++) {
                uint32_t v = h ? v1 : v0;
                if (v > bs[TOPT - 1]) {
                    uint32_t cv = v;
                    #pragma unroll
                    for (int r = 0; r < TOPT; r++) {
                        if (cv > bs[r]) { uint32_t t = bs[r]; bs[r] = cv; cv = t; }
                    }
                }
            }
        }
        #pragma unroll
        for (int r = 0; r < TOPT; r++)
            scr[(tq * 4 + tsg) * TOPT + r] = bs[r];
    }
    __syncthreads();

    // ---- leader: merge 4 sorted packed top-8 lists -> top-8, write ----
    if (tsg == 0) {
        int q = qtile * QT + tq;
        size_t ob = (((size_t)sp * Q_ + q) * NPT + ptile) * TOPT;
        int h0 = 0, h1 = 0, h2 = 0, h3 = 0;
        const uint32_t* L = scr + (size_t)tq * 4 * TOPT;
        #pragma unroll
        for (int r = 0; r < TOPT; r++) {
            uint32_t best = 0u; int bj = 0;
            #define TRYM(j, h) { uint32_t v = ((h) < TOPT) ? L[(j) * TOPT + (h)] : 0u; \
                                 if (v > best) { best = v; bj = (j); } }
            TRYM(0, h0) TRYM(1, h1) TRYM(2, h2) TRYM(3, h3)
            #undef TRYM
            g_cand[ob + r] = best;
            if      (bj == 0) h0++;
            else if (bj == 1) h1++;
            else if (bj == 2) h2++;
            else              h3++;
        }
    }
}

// ============================================================
// Kernel 2: per (s',q): packed tournament over 128 sorted top-8
// lists -> approx top-32, exact f32 rescore, exact top-11.
// grid 4096, block 512
// ============================================================
__global__ __launch_bounds__(512) void select_kernel(const float* __restrict__ ent) {
    __shared__ uint32_t cp_t[TOPT][NPT];   // [rank][list] packed
    __shared__ int      sel_ix[MSEL];
    __shared__ float    fsc[MSEL];

    const int tid = threadIdx.x;
    const int pair = blockIdx.x;
    const int sp = pair >> 10, q = pair & 1023;
    size_t base = ((size_t)sp * Q_ + q) * (size_t)(NPT * TOPT);

    for (int e = tid; e < NPT * TOPT; e += 512)
        cp_t[e & 7][e >> 3] = g_cand[base + e];
    __syncthreads();

    // warp 0: tournament; lane owns 4 lists with packed register heads
    if (tid < 32) {
        int      h[4];
        uint32_t hv[4];
        #pragma unroll
        for (int j = 0; j < 4; j++) { h[j] = 0; hv[j] = cp_t[0][tid * 4 + j]; }
        for (int r = 0; r < MSEL; r++) {
            uint32_t best = hv[0]; int bj = 0;
            #pragma unroll
            for (int j = 1; j < 4; j++) if (hv[j] > best) { best = hv[j]; bj = j; }
            uint32_t bv = best; int bl = tid;
            #pragma unroll
            for (int off = 16; off > 0; off >>= 1) {
                uint32_t ov = __shfl_down_sync(0xffffffffu, bv, off);
                int      ol = __shfl_down_sync(0xffffffffu, bl, off);
                if (ov > bv) { bv = ov; bl = ol; }
            }
            bl = __shfl_sync(0xffffffffu, bl, 0);
            if (tid == bl) {
                int list = tid * 4 + bj;
                sel_ix[r] = (int)(hv[bj] & 0xFFFFu);
                h[bj]++;
                hv[bj] = (h[bj] < TOPT) ? cp_t[h[bj]][list] : 0u;
            }
            __syncwarp();
        }
    }
    __syncthreads();

    // exact f32 rescore: 16 threads per candidate, 32 candidates
    {
        int c = tid >> 4, part = tid & 15;
        int p = sel_ix[c];
        const float4* qv = (const float4*)(g_qvec + (size_t)q * D_ + part * 16);
        const float4* ev = (const float4*)(ent + ((size_t)sp * P_ + p) * D_ + part * 16);
        float accv = 0.f;
        #pragma unroll
        for (int i = 0; i < 4; i++) {
            float4 a = qv[i], e = ev[i];
            accv = fmaf(a.x, e.x, fmaf(a.y, e.y, fmaf(a.z, e.z, fmaf(a.w, e.w, accv))));
        }
        #pragma unroll
        for (int off = 8; off > 0; off >>= 1)
            accv += __shfl_down_sync(0xffffffffu, accv, off, 16);
        if (part == 0) fsc[c] = accv;
    }
    __syncthreads();

    // warp 0: exact top-11 of 32
    if (tid < 32) {
        float v = fsc[tid];
        int ix = sel_ix[tid];
        size_t ob = ((size_t)sp * Q_ + q) * NB;
        for (int r = 0; r < NB; r++) {
            float bv = v; int bl = tid;
            #pragma unroll
            for (int off = 16; off > 0; off >>= 1) {
                float ov = __shfl_down_sync(0xffffffffu, bv, off);
                int   ol = __shfl_down_sync(0xffffffffu, bl, off);
                if (ov > bv) { bv = ov; bl = ol; }
            }
            bl = __shfl_sync(0xffffffffu, bl, 0);
            float wv = __shfl_sync(0xffffffffu, v, bl);
            int   wi = __shfl_sync(0xffffffffu, ix, bl);
            if (tid == 0) { g_best_sc[ob + r] = wv; g_best_ix[ob + r] = wi; }
            if (tid == bl) v = NEG_INF;
            __syncwarp();
        }
    }
}

// ============================================================
// Kernel 3: per (s,b) merge 4 x 11 -> top-10; write output
// ============================================================
__global__ void final_kernel(float* __restrict__ out) {
    int q = blockIdx.x * blockDim.x + threadIdx.x;
    if (q >= Q_) return;
    float bs[KOUT]; int bg[KOUT];
    #pragma unroll
    for (int r = 0; r < KOUT; r++) { bs[r] = NEG_INF; bg[r] = -1; }
    for (int sp = 0; sp < S_; sp++) {
        size_t base = ((size_t)sp * Q_ + q) * NB;
        for (int r = 0; r < NB; r++) {
            float v = g_best_sc[base + r];
            if (v > bs[KOUT - 1]) {
                int gid = g_best_ix[base + r] * S_ + sp;
                float cv = v; int ci = gid;
                #pragma unroll
                for (int k = 0; k < KOUT; k++) {
                    if (cv > bs[k]) {
                        float t0 = bs[k]; int t1 = bg[k];
                        bs[k] = cv; bg[k] = ci; cv = t0; ci = t1;
                    }
                }
            }
        }
    }
    #pragma unroll
    for (int k = 0; k < KOUT; k++) {
        out[q * KOUT + k]             = (float)bg[k];
        out[Q_ * KOUT + q * KOUT + k] = bs[k];
    }
}

// ============================================================
extern "C" void kernel_launch(void* const* d_in, const int* in_sizes, int n_in,
                              void* d_out, int out_size) {
    const int*   relation = (const int*)d_in[0];
    const int*   head     = (const int*)d_in[1];
    const float* ent      = (const float*)d_in[2];
    const float* rel      = (const float*)d_in[3];
    float* out = (float*)d_out;

    cudaFuncSetAttribute(score_kernel, cudaFuncAttributeMaxDynamicSharedMemorySize, SM_TOTAL);

    conv_kernel<<<(int)(((size_t)S_ * P_ * D_ / 4) / 256), 256>>>(ent);
    qvec_kernel<<<Q_, D_>>>(relation, head, ent, rel);
    dim3 g1(NQT, NPT, S_);
    score_kernel<<<g1, 512, SM_TOTAL>>>();
    select_kernel<<<S_ * Q_, 512>>>(ent);
    final_kernel<<<4, 256>>>(out);
}